// round 17
// baseline (speedup 1.0000x reference)
#include <cuda_runtime.h>
#include <cuda_fp16.h>
#include <cstdint>

// GroupFC: h[B,G,D], W[G,D,K], out[B,G,K]; out = normalize(h) @ normalize_d(W)
#define B_SZ 256
#define G_SZ 100
#define D_SZ 768
#define K_SZ 128

#define BM 128
#define BN 64
#define BK 32
#define NT (D_SZ / BK)           // 24
#define SAU 20                   // uints per A row: 16 fp16x2 + 4 pad (80 B)
#define SA_ST (BM * SAU)         // 2560 uints / stage (A fp16, 2 stages)
#define SA_BYTES (SA_ST * 4)     // 10240
#define SBF 68                   // floats per B row: 64 + 4 pad
#define SB_ST (BK * SBF)         // 2176 floats / stage (B fp32, 4 stages)
#define SB_BYTES (SB_ST * 4)     // 8704

// dynamic smem (uint32 words): A 2 stages | B 4-ring | hsum 128 | wsum 64
#define OFF_B   (2 * SA_ST)
#define OFF_HS  (OFF_B + 4 * SB_ST)
#define OFF_WS  (OFF_HS + BM)
#define SMEM_BYTES ((OFF_WS + BN) * 4)   // 56064 B  (x3 CTAs = 168K <= 228K)

// pack two floats to fp16x2 (lo = first element).
__device__ __forceinline__ uint32_t packh2(float lo, float hi) {
    uint32_t u;
    asm("cvt.rn.f16x2.f32 %0, %1, %2;" : "=r"(u) : "f"(hi), "f"(lo));
    return u;
}
__device__ __forceinline__ void cp16(uint32_t saddr, const float* gaddr) {
    asm volatile("cp.async.cg.shared.global [%0], [%1], 16;"
                 :: "r"(saddr), "l"(gaddr));
}

__global__ __launch_bounds__(256, 3)
void groupfc_h2(const float* __restrict__ h,
                const float* __restrict__ w,
                float* __restrict__ out) {
    extern __shared__ uint32_t smem[];
    uint32_t* uA = smem;
    float* fB    = reinterpret_cast<float*>(smem + OFF_B);
    float* hsum  = reinterpret_cast<float*>(smem + OFF_HS);
    float* wsum  = reinterpret_cast<float*>(smem + OFF_WS);
    const uint32_t uA_s = (uint32_t)__cvta_generic_to_shared(uA);
    const uint32_t fB_s = (uint32_t)__cvta_generic_to_shared(fB);

    const int g    = blockIdx.z;
    const int m0   = blockIdx.x * BM;
    const int n0   = blockIdx.y * BN;
    const int tid  = threadIdx.x;
    const int lane = tid & 31;
    const int warp = tid >> 5;
    const int gid  = lane >> 2;            // 0..7
    const int tig  = lane & 3;             // 0..3
    const int wm   = warp >> 2;            // 0..1 : rows wm*64..+64
    const int wn   = warp & 3;             // 0..3 : cols wn*16..+16

    const float* hbase = h + ((size_t)m0 * G_SZ + (size_t)g) * D_SZ;
    const float* wgrp  = w + (size_t)g * D_SZ * K_SZ + n0;
    const size_t hstride = (size_t)G_SZ * D_SZ;

    const int arow = tid >> 3;             // A rows {arow+32j}, j=0..3
    const int ac4  = tid & 7;              // A k-chunk of 4

    // per-lane ldmatrix byte offset within a fragment block
    const uint32_t a_lane = (uint32_t)((lane & 7) + ((lane >> 3) & 1) * 8) * 80u
                          + (uint32_t)((lane >> 4) & 1) * 16u;

    float acc[4][2][4];
#pragma unroll
    for (int mf = 0; mf < 4; mf++)
#pragma unroll
        for (int nf = 0; nf < 2; nf++)
#pragma unroll
            for (int q = 0; q < 4; q++) acc[mf][nf][q] = 0.f;

    float asq[4] = {0.f, 0.f, 0.f, 0.f};
    float wsq[2] = {0.f, 0.f};
    float4 rA[4];

    auto cpB = [&](int t) {                // gmem -> smem 4-ring (RF-bypass)
        const int s = t & 3;
#pragma unroll
        for (int j = 0; j < 2; j++) {
            int id  = tid + j * 256;       // 0..511 chunks of 16B
            int row = id >> 4;             // 0..31 (d in tile)
            int c4  = id & 15;             // 16B column chunk
            cp16(fB_s + (uint32_t)(s * SB_BYTES + row * (SBF * 4) + c4 * 16),
                 wgrp + (size_t)(t * BK + row) * K_SZ + c4 * 4);
        }
        asm volatile("cp.async.commit_group;");
    };
    auto ldgA = [&](int t) {
#pragma unroll
        for (int j = 0; j < 4; j++)
            rA[j] = *reinterpret_cast<const float4*>(
                hbase + (size_t)(arow + 32 * j) * hstride + t * BK + ac4 * 4);
    };
    auto stsA = [&](int s) {               // s = STAGE (0/1); fused h sumsq
        uint32_t* da = uA + s * SA_ST;
#pragma unroll
        for (int j = 0; j < 4; j++) {
            float4 v = rA[j];
            asq[j] = fmaf(v.x, v.x, fmaf(v.y, v.y,
                     fmaf(v.z, v.z, fmaf(v.w, v.w, asq[j]))));
            uint2 u = make_uint2(packh2(v.x, v.y), packh2(v.z, v.w));
            *reinterpret_cast<uint2*>(da + (arow + 32 * j) * SAU + ac4 * 2) = u;
        }
    };
    auto half = [&](int t, int ks) {       // one k16 step over all warp frags
        const uint32_t abase = uA_s + (t & 1) * SA_BYTES
                             + (uint32_t)(wm * 64) * 80u + a_lane
                             + (uint32_t)(ks * 32);
        const float* cB = fB + (t & 3) * SB_ST;
        const float* br = cB + (ks * 16 + 2 * tig) * SBF + wn * 16 + gid;
        uint32_t bf[2][2];
#pragma unroll
        for (int nf = 0; nf < 2; nf++) {
            float b00 = br[nf * 8];
            float b01 = br[nf * 8 + SBF];
            float b10 = br[nf * 8 + 8 * SBF];
            float b11 = br[nf * 8 + 9 * SBF];
            if (wm == 0)                   // each B element seen once by wm=0
                wsq[nf] = fmaf(b00, b00, fmaf(b01, b01,
                          fmaf(b10, b10, fmaf(b11, b11, wsq[nf]))));
            bf[nf][0] = packh2(b00, b01);
            bf[nf][1] = packh2(b10, b11);
        }
#pragma unroll
        for (int mf = 0; mf < 4; mf++) {
            uint32_t af0, af1, af2, af3;
            asm volatile(
                "ldmatrix.sync.aligned.m8n8.x4.shared.b16 {%0,%1,%2,%3}, [%4];"
                : "=r"(af0), "=r"(af1), "=r"(af2), "=r"(af3)
                : "r"(abase + (uint32_t)(mf * 16) * 80u));
#pragma unroll
            for (int nf = 0; nf < 2; nf++) {
                asm volatile(
                    "mma.sync.aligned.m16n8k16.row.col.f32.f16.f16.f32 "
                    "{%0,%1,%2,%3}, {%4,%5,%6,%7}, {%8,%9}, {%0,%1,%2,%3};"
                    : "+f"(acc[mf][nf][0]), "+f"(acc[mf][nf][1]),
                      "+f"(acc[mf][nf][2]), "+f"(acc[mf][nf][3])
                    : "r"(af0), "r"(af1), "r"(af2), "r"(af3),
                      "r"(bf[nf][0]), "r"(bf[nf][1]));
            }
        }
    };

    // ---- prologue: B tiles 0..2 in flight; A tile 0 staged ----
    cpB(0); cpB(1); cpB(2);
    ldgA(0); stsA(0);

    // ---- mainloop: one barrier/tile; B lands 3 tiles ahead; mid-iter STS ----
    for (int t = 0; t < NT; t++) {
        if (t + 1 < NT) ldgA(t + 1);
        // confirm B(t): keep at most the (NT-1-t, capped 2) newest pending
        if (t < NT - 2)
            asm volatile("cp.async.wait_group 2;");
        else if (t == NT - 2)
            asm volatile("cp.async.wait_group 1;");
        else
            asm volatile("cp.async.wait_group 0;");
        __syncthreads();
        if (t + 3 < NT) cpB(t + 3);        // slot (t+3)&3: reader t-1 done ^
        half(t, 0);
        if (t + 1 < NT) stsA((t + 1) & 1); // early STS: drains during ks1
        half(t, 1);
    }

    // ---- norm reductions ----
#pragma unroll
    for (int j = 0; j < 4; j++) {          // 8 lanes share each h row
        float s = asq[j];
        s += __shfl_xor_sync(0xffffffffu, s, 1);
        s += __shfl_xor_sync(0xffffffffu, s, 2);
        s += __shfl_xor_sync(0xffffffffu, s, 4);
        if ((lane & 7) == 0) hsum[arow + 32 * j] = s;
    }
    if (wm == 0) {                         // 4 tig lanes share each w column
#pragma unroll
        for (int nf = 0; nf < 2; nf++) {
            float s = wsq[nf];
            s += __shfl_xor_sync(0xffffffffu, s, 1);
            s += __shfl_xor_sync(0xffffffffu, s, 2);
            if (tig == 0) wsum[wn * 16 + nf * 8 + gid] = s;
        }
    }
    __syncthreads();

    // ---- epilogue: scale by 1/(||h_row||*||w_col||), store ----
#pragma unroll
    for (int mf = 0; mf < 4; mf++) {
        int r  = wm * 64 + mf * 16 + gid;
        int b0 = m0 + r;
        float rh0 = 1.0f / fmaxf(sqrtf(hsum[r]), 1e-12f);
        float rh1 = 1.0f / fmaxf(sqrtf(hsum[r + 8]), 1e-12f);
        float* o0 = out + ((size_t)b0 * G_SZ + g) * K_SZ + n0;
        float* o1 = o0 + (size_t)8 * G_SZ * K_SZ;
#pragma unroll
        for (int nf = 0; nf < 2; nf++) {
            int c = wn * 16 + nf * 8 + tig * 2;
            float rw0 = 1.0f / fmaxf(sqrtf(wsum[c]), 1e-12f);
            float rw1 = 1.0f / fmaxf(sqrtf(wsum[c + 1]), 1e-12f);
            float2 v0 = make_float2(acc[mf][nf][0] * rh0 * rw0,
                                    acc[mf][nf][1] * rh0 * rw1);
            float2 v1 = make_float2(acc[mf][nf][2] * rh1 * rw0,
                                    acc[mf][nf][3] * rh1 * rw1);
            *reinterpret_cast<float2*>(o0 + c) = v0;
            *reinterpret_cast<float2*>(o1 + c) = v1;
        }
    }
}

extern "C" void kernel_launch(void* const* d_in, const int* in_sizes, int n_in,
                              void* d_out, int out_size) {
    const float* h = (const float*)d_in[0];   // [B,G,D]
    const float* w = (const float*)d_in[1];   // [G,D,K]
    float* out     = (float*)d_out;           // [B,G,K]
    (void)in_sizes; (void)n_in; (void)out_size;

    cudaFuncSetAttribute(groupfc_h2,
                         cudaFuncAttributeMaxDynamicSharedMemorySize, SMEM_BYTES);
    groupfc_h2<<<dim3(B_SZ / BM, K_SZ / BN, G_SZ), 256, SMEM_BYTES>>>(h, w, out);
}